// round 14
// baseline (speedup 1.0000x reference)
#include <cuda_runtime.h>
#include <cstdint>
#include <math.h>

// N=8 (7 completed blocks + partial), D=2048, B*L=8192 rows.
// R13 structure (grid=BL, 3 CTAs/SM, TMA bulk stage-in, 4 mbarrier phases,
// packed-butterfly reduction) + level-1 folds moved into the phases and
// L2 evict-first cache hint on the single-use input streams.
#define NB 8
#define DDIM 2048
#define THREADS 256
#define ROW_BYTES (DDIM * 4)              // 8 KB per block slice
#define SMEM_BYTES (NB * DDIM * 4)        // 64 KB data stage
#define NPHASE 4

__device__ __forceinline__ void mbar_wait(unsigned int mb) {
    unsigned int done;
    asm volatile(
        "{\n\t"
        ".reg .pred p;\n\t"
        "mbarrier.try_wait.parity.acquire.cta.shared::cta.b64 p, [%1], 0;\n\t"
        "selp.b32 %0, 1, 0, p;\n\t"
        "}" : "=r"(done) : "r"(mb) : "memory");
    if (!done) {
        asm volatile(
            "{\n\t"
            ".reg .pred P1;\n\t"
            "WAIT_LOOP_%=:\n\t"
            "mbarrier.try_wait.parity.acquire.cta.shared::cta.b64 P1, [%0], 0, 0x989680;\n\t"
            "@P1 bra.uni WAIT_DONE_%=;\n\t"
            "bra.uni WAIT_LOOP_%=;\n\t"
            "WAIT_DONE_%=:\n\t"
            "}" :: "r"(mb) : "memory");
    }
}

__global__ __launch_bounds__(THREADS, 3)
void attn_residual_kernel(const float* __restrict__ blocks,     // [7, BL, D]
                          const float* __restrict__ partial,    // [BL, D]
                          const float* __restrict__ norm_scale, // [D]
                          const float* __restrict__ proj,       // [D]
                          float* __restrict__ out,              // [BL, D]
                          int BL)
{
    extern __shared__ float sv[];         // [NB][DDIM], 16B aligned
    __shared__ __align__(8) unsigned long long mbar[NPHASE];
    __shared__ float red[THREADS / 32][16];
    __shared__ float fin[16];

    const int row  = blockIdx.x;
    const int t    = threadIdx.x;
    const int lane = t & 31;
    const int warp = t >> 5;

    const size_t rowOff  = (size_t)row * DDIM;
    const size_t nStride = (size_t)BL * DDIM;

    const int d0 = t * 4;            // [0, 1024)
    const int d1 = 1024 + t * 4;     // [1024, 2048)

    unsigned int svb, mbb;
    asm("{ .reg .u64 tmp; cvta.to.shared.u64 tmp, %1; cvt.u32.u64 %0, tmp; }"
        : "=r"(svb) : "l"(sv));
    asm("{ .reg .u64 tmp; cvta.to.shared.u64 tmp, %1; cvt.u32.u64 %0, tmp; }"
        : "=r"(mbb) : "l"(&mbar[0]));

    // ---- Init mbarriers, then bulk-copy 8 contiguous 8KB slices ----
    if (t == 0) {
#pragma unroll
        for (int p = 0; p < NPHASE; p++)
            asm volatile("mbarrier.init.shared.b64 [%0], 1;"
                         :: "r"(mbb + 8u * p) : "memory");
    }
    __syncthreads();

    if (t == 0) {
        unsigned long long pol;
        asm("createpolicy.fractional.L2::evict_first.b64 %0, 1.0;" : "=l"(pol));
#pragma unroll
        for (int p = 0; p < NPHASE; p++)
            asm volatile("mbarrier.arrive.expect_tx.shared.b64 _, [%0], %1;"
                         :: "r"(mbb + 8u * p), "r"(2 * ROW_BYTES) : "memory");
#pragma unroll
        for (int n = 0; n < NB; n++) {
            const float* src = (n < NB - 1)
                                 ? (blocks + (size_t)n * nStride + rowOff)
                                 : (partial + rowOff);
            asm volatile(
                "cp.async.bulk.shared::cluster.global.mbarrier::complete_tx::bytes"
                ".L2::cache_hint [%0], [%1], %2, [%3], %4;"
                :: "r"(svb + (unsigned)(n * ROW_BYTES)), "l"(src),
                   "r"(ROW_BYTES), "r"(mbb + 8u * (n >> 1)), "l"(pol)
                : "memory");
        }
    }

    // q[d] = proj[d] * norm_scale[d] (overlaps with bulk copies)
    float4 q0, q1;
    {
        float4 p = *(const float4*)(proj + d0);
        float4 s = *(const float4*)(norm_scale + d0);
        q0 = make_float4(p.x * s.x, p.y * s.y, p.z * s.z, p.w * s.w);
        p = *(const float4*)(proj + d1);
        s = *(const float4*)(norm_scale + d1);
        q1 = make_float4(p.x * s.x, p.y * s.y, p.z * s.z, p.w * s.w);
    }

    // v[n]: after PROC, holds dot partial; lvl-1 fold merges with ssq (v-hi).
    float v[16];

#define PROC(n)                                                              \
    do {                                                                     \
        float4 a = *(const float4*)(sv + (n) * DDIM + d0);                   \
        float4 b = *(const float4*)(sv + (n) * DDIM + d1);                   \
        v[n]     = q0.x * a.x + q0.y * a.y + q0.z * a.z + q0.w * a.w         \
                 + q1.x * b.x + q1.y * b.y + q1.z * b.z + q1.w * b.w;        \
        v[8+(n)] = a.x * a.x + a.y * a.y + a.z * a.z + a.w * a.w             \
                 + b.x * b.x + b.y * b.y + b.z * b.z + b.w * b.w;            \
    } while (0)

    // Level-1 butterfly fold (xor 16) for slice n: merge v[n] with v[n+8].
#define FOLD1(n)                                                             \
    do {                                                                     \
        bool hi = (lane & 16);                                               \
        float x = hi ? v[(n) + 8] : v[n];                                    \
        float y = hi ? v[n] : v[(n) + 8];                                    \
        v[n] = x + __shfl_xor_sync(0xffffffffu, y, 16);                      \
    } while (0)

    // ---- 4 phases: wait 16KB, compute pair + lvl-1 fold (overlaps rest) ----
    mbar_wait(mbb + 0);  PROC(0); PROC(1); FOLD1(0); FOLD1(1);
    mbar_wait(mbb + 8);  PROC(2); PROC(3); FOLD1(2); FOLD1(3);
    mbar_wait(mbb + 16); PROC(4); PROC(5); FOLD1(4); FOLD1(5);
    mbar_wait(mbb + 24); PROC(6); PROC(7); FOLD1(6); FOLD1(7);
#undef PROC
#undef FOLD1

    // ---- Remaining butterfly levels: 8 vars in 8 shuffles ----
#pragma unroll
    for (int j = 0; j < 4; j++) {
        bool hi = (lane & 8);
        float x = hi ? v[j + 4] : v[j];
        float y = hi ? v[j] : v[j + 4];
        v[j] = x + __shfl_xor_sync(0xffffffffu, y, 8);
    }
#pragma unroll
    for (int j = 0; j < 2; j++) {
        bool hi = (lane & 4);
        float x = hi ? v[j + 2] : v[j];
        float y = hi ? v[j] : v[j + 2];
        v[j] = x + __shfl_xor_sync(0xffffffffu, y, 4);
    }
    float r;
    {
        bool hi = (lane & 2);
        float x = hi ? v[1] : v[0];
        float y = hi ? v[0] : v[1];
        r = x + __shfl_xor_sync(0xffffffffu, y, 2);
    }
    r += __shfl_xor_sync(0xffffffffu, r, 1);

    // lane -> which of the 16 sums this lane now holds
    const int vi = ((lane >> 4) & 1) * 8 + ((lane >> 3) & 1) * 4
                 + ((lane >> 2) & 1) * 2 + ((lane >> 1) & 1);
    if ((lane & 1) == 0) red[warp][vi] = r;

    __syncthreads();
    if (t < 16) {
        float s = 0.f;
#pragma unroll
        for (int w = 0; w < THREADS / 32; w++) s += red[w][t];
        fin[t] = s;
    }
    __syncthreads();

    // ---- Softmax over n (redundant per-thread; trivial) ----
    float wgt[NB];
    float mx = -INFINITY;
#pragma unroll
    for (int n = 0; n < NB; n++) {
        float rms = sqrtf(fin[8 + n] * (1.0f / DDIM) + 1e-6f);
        wgt[n] = fin[n] / rms;
        mx = fmaxf(mx, wgt[n]);
    }
    float wsum = 0.f;
#pragma unroll
    for (int n = 0; n < NB; n++) {
        wgt[n] = __expf(wgt[n] - mx);
        wsum += wgt[n];
    }
    const float inv = 1.0f / wsum;

    // ---- Pass 2: weighted sum from smem; streaming store ----
    float4 o0 = make_float4(0.f, 0.f, 0.f, 0.f);
    float4 o1 = make_float4(0.f, 0.f, 0.f, 0.f);
#pragma unroll
    for (int n = 0; n < NB; n++) {
        float w = wgt[n] * inv;
        float4 a = *(const float4*)(sv + n * DDIM + d0);
        float4 b = *(const float4*)(sv + n * DDIM + d1);
        o0.x += w * a.x; o0.y += w * a.y; o0.z += w * a.z; o0.w += w * a.w;
        o1.x += w * b.x; o1.y += w * b.y; o1.z += w * b.z; o1.w += w * b.w;
    }
    __stcs((float4*)(out + rowOff + d0), o0);
    __stcs((float4*)(out + rowOff + d1), o1);
}

extern "C" void kernel_launch(void* const* d_in, const int* in_sizes, int n_in,
                              void* d_out, int out_size)
{
    const float* blocks     = (const float*)d_in[0];
    const float* partial    = (const float*)d_in[1];
    const float* norm_scale = (const float*)d_in[2];
    const float* proj       = (const float*)d_in[3];
    float* out              = (float*)d_out;

    const int BL = in_sizes[1] / DDIM;

    static int configured = 0;
    if (!configured) {
        cudaFuncSetAttribute(attn_residual_kernel,
                             cudaFuncAttributeMaxDynamicSharedMemorySize,
                             SMEM_BYTES);
        configured = 1;
    }

    attn_residual_kernel<<<BL, THREADS, SMEM_BYTES>>>(blocks, partial,
                                                      norm_scale, proj,
                                                      out, BL);
}

// round 15
// speedup vs baseline: 1.0259x; 1.0259x over previous
#include <cuda_runtime.h>
#include <cstdint>
#include <math.h>

// FINAL: N=8 (7 completed blocks + partial), D=2048, B*L=8192 rows.
// grid=BL, 3 CTAs/SM, TMA bulk stage-in (8x8KB), 4 mbarrier phases of 2
// slices with compute+level-1 butterfly folded under TMA arrivals, packed
// 16-scalar butterfly reduction (16 SHFL total), L2 evict-first on inputs,
// rsqrtf-based RMS, streaming stores.
// Session: 105 -> 100.4 -> 98.8 -> 97.4 -> 94.9 -> 92.4 us.
#define NB 8
#define DDIM 2048
#define THREADS 256
#define ROW_BYTES (DDIM * 4)              // 8 KB per block slice
#define SMEM_BYTES (NB * DDIM * 4)        // 64 KB data stage
#define NPHASE 4

__device__ __forceinline__ void mbar_wait(unsigned int mb) {
    unsigned int done;
    asm volatile(
        "{\n\t"
        ".reg .pred p;\n\t"
        "mbarrier.try_wait.parity.acquire.cta.shared::cta.b64 p, [%1], 0;\n\t"
        "selp.b32 %0, 1, 0, p;\n\t"
        "}" : "=r"(done) : "r"(mb) : "memory");
    if (!done) {
        asm volatile(
            "{\n\t"
            ".reg .pred P1;\n\t"
            "WAIT_LOOP_%=:\n\t"
            "mbarrier.try_wait.parity.acquire.cta.shared::cta.b64 P1, [%0], 0, 0x989680;\n\t"
            "@P1 bra.uni WAIT_DONE_%=;\n\t"
            "bra.uni WAIT_LOOP_%=;\n\t"
            "WAIT_DONE_%=:\n\t"
            "}" :: "r"(mb) : "memory");
    }
}

__global__ __launch_bounds__(THREADS, 3)
void attn_residual_kernel(const float* __restrict__ blocks,     // [7, BL, D]
                          const float* __restrict__ partial,    // [BL, D]
                          const float* __restrict__ norm_scale, // [D]
                          const float* __restrict__ proj,       // [D]
                          float* __restrict__ out,              // [BL, D]
                          int BL)
{
    extern __shared__ float sv[];         // [NB][DDIM], 16B aligned
    __shared__ __align__(8) unsigned long long mbar[NPHASE];
    __shared__ float red[THREADS / 32][16];
    __shared__ float fin[16];

    const int row  = blockIdx.x;
    const int t    = threadIdx.x;
    const int lane = t & 31;
    const int warp = t >> 5;

    const size_t rowOff  = (size_t)row * DDIM;
    const size_t nStride = (size_t)BL * DDIM;

    const int d0 = t * 4;            // [0, 1024)
    const int d1 = 1024 + t * 4;     // [1024, 2048)

    unsigned int svb, mbb;
    asm("{ .reg .u64 tmp; cvta.to.shared.u64 tmp, %1; cvt.u32.u64 %0, tmp; }"
        : "=r"(svb) : "l"(sv));
    asm("{ .reg .u64 tmp; cvta.to.shared.u64 tmp, %1; cvt.u32.u64 %0, tmp; }"
        : "=r"(mbb) : "l"(&mbar[0]));

    // ---- Init mbarriers, then bulk-copy 8 contiguous 8KB slices ----
    if (t == 0) {
#pragma unroll
        for (int p = 0; p < NPHASE; p++)
            asm volatile("mbarrier.init.shared.b64 [%0], 1;"
                         :: "r"(mbb + 8u * p) : "memory");
    }
    __syncthreads();

    if (t == 0) {
        unsigned long long pol;
        asm("createpolicy.fractional.L2::evict_first.b64 %0, 1.0;" : "=l"(pol));
#pragma unroll
        for (int p = 0; p < NPHASE; p++)
            asm volatile("mbarrier.arrive.expect_tx.shared.b64 _, [%0], %1;"
                         :: "r"(mbb + 8u * p), "r"(2 * ROW_BYTES) : "memory");
#pragma unroll
        for (int n = 0; n < NB; n++) {
            const float* src = (n < NB - 1)
                                 ? (blocks + (size_t)n * nStride + rowOff)
                                 : (partial + rowOff);
            asm volatile(
                "cp.async.bulk.shared::cluster.global.mbarrier::complete_tx::bytes"
                ".L2::cache_hint [%0], [%1], %2, [%3], %4;"
                :: "r"(svb + (unsigned)(n * ROW_BYTES)), "l"(src),
                   "r"(ROW_BYTES), "r"(mbb + 8u * (n >> 1)), "l"(pol)
                : "memory");
        }
    }

    // q[d] = proj[d] * norm_scale[d] (overlaps with bulk copies)
    float4 q0, q1;
    {
        float4 p = *(const float4*)(proj + d0);
        float4 s = *(const float4*)(norm_scale + d0);
        q0 = make_float4(p.x * s.x, p.y * s.y, p.z * s.z, p.w * s.w);
        p = *(const float4*)(proj + d1);
        s = *(const float4*)(norm_scale + d1);
        q1 = make_float4(p.x * s.x, p.y * s.y, p.z * s.z, p.w * s.w);
    }

    // v[n]: after PROC, holds dot partial; lvl-1 fold merges with ssq (v-hi).
    float v[16];

#define PROC(n)                                                              \
    do {                                                                     \
        float4 a = *(const float4*)(sv + (n) * DDIM + d0);                   \
        float4 b = *(const float4*)(sv + (n) * DDIM + d1);                   \
        v[n]     = q0.x * a.x + q0.y * a.y + q0.z * a.z + q0.w * a.w         \
                 + q1.x * b.x + q1.y * b.y + q1.z * b.z + q1.w * b.w;        \
        v[8+(n)] = a.x * a.x + a.y * a.y + a.z * a.z + a.w * a.w             \
                 + b.x * b.x + b.y * b.y + b.z * b.z + b.w * b.w;            \
    } while (0)

    // Level-1 butterfly fold (xor 16) for slice n: merge v[n] with v[n+8].
#define FOLD1(n)                                                             \
    do {                                                                     \
        bool hi = (lane & 16);                                               \
        float x = hi ? v[(n) + 8] : v[n];                                    \
        float y = hi ? v[n] : v[(n) + 8];                                    \
        v[n] = x + __shfl_xor_sync(0xffffffffu, y, 16);                      \
    } while (0)

    // ---- 4 phases: wait 16KB, compute pair + lvl-1 fold (overlaps rest) ----
    mbar_wait(mbb + 0);  PROC(0); PROC(1); FOLD1(0); FOLD1(1);
    mbar_wait(mbb + 8);  PROC(2); PROC(3); FOLD1(2); FOLD1(3);
    mbar_wait(mbb + 16); PROC(4); PROC(5); FOLD1(4); FOLD1(5);
    mbar_wait(mbb + 24); PROC(6); PROC(7); FOLD1(6); FOLD1(7);
#undef PROC
#undef FOLD1

    // ---- Remaining butterfly levels: 8 vars in 8 shuffles ----
#pragma unroll
    for (int j = 0; j < 4; j++) {
        bool hi = (lane & 8);
        float x = hi ? v[j + 4] : v[j];
        float y = hi ? v[j] : v[j + 4];
        v[j] = x + __shfl_xor_sync(0xffffffffu, y, 8);
    }
#pragma unroll
    for (int j = 0; j < 2; j++) {
        bool hi = (lane & 4);
        float x = hi ? v[j + 2] : v[j];
        float y = hi ? v[j] : v[j + 2];
        v[j] = x + __shfl_xor_sync(0xffffffffu, y, 4);
    }
    float r;
    {
        bool hi = (lane & 2);
        float x = hi ? v[1] : v[0];
        float y = hi ? v[0] : v[1];
        r = x + __shfl_xor_sync(0xffffffffu, y, 2);
    }
    r += __shfl_xor_sync(0xffffffffu, r, 1);

    // lane -> which of the 16 sums this lane now holds
    const int vi = ((lane >> 4) & 1) * 8 + ((lane >> 3) & 1) * 4
                 + ((lane >> 2) & 1) * 2 + ((lane >> 1) & 1);
    if ((lane & 1) == 0) red[warp][vi] = r;

    __syncthreads();
    if (t < 16) {
        float s = 0.f;
#pragma unroll
        for (int w = 0; w < THREADS / 32; w++) s += red[w][t];
        fin[t] = s;
    }
    __syncthreads();

    // ---- Softmax over n (redundant per-thread; rsqrt-based RMS) ----
    float wgt[NB];
    float mx = -INFINITY;
#pragma unroll
    for (int n = 0; n < NB; n++) {
        wgt[n] = fin[n] * rsqrtf(fin[8 + n] * (1.0f / DDIM) + 1e-6f);
        mx = fmaxf(mx, wgt[n]);
    }
    float wsum = 0.f;
#pragma unroll
    for (int n = 0; n < NB; n++) {
        wgt[n] = __expf(wgt[n] - mx);
        wsum += wgt[n];
    }
    const float inv = 1.0f / wsum;

    // ---- Pass 2: weighted sum from smem; streaming store ----
    float4 o0 = make_float4(0.f, 0.f, 0.f, 0.f);
    float4 o1 = make_float4(0.f, 0.f, 0.f, 0.f);
#pragma unroll
    for (int n = 0; n < NB; n++) {
        float w = wgt[n] * inv;
        float4 a = *(const float4*)(sv + n * DDIM + d0);
        float4 b = *(const float4*)(sv + n * DDIM + d1);
        o0.x += w * a.x; o0.y += w * a.y; o0.z += w * a.z; o0.w += w * a.w;
        o1.x += w * b.x; o1.y += w * b.y; o1.z += w * b.z; o1.w += w * b.w;
    }
    __stcs((float4*)(out + rowOff + d0), o0);
    __stcs((float4*)(out + rowOff + d1), o1);
}

extern "C" void kernel_launch(void* const* d_in, const int* in_sizes, int n_in,
                              void* d_out, int out_size)
{
    const float* blocks     = (const float*)d_in[0];
    const float* partial    = (const float*)d_in[1];
    const float* norm_scale = (const float*)d_in[2];
    const float* proj       = (const float*)d_in[3];
    float* out              = (float*)d_out;

    const int BL = in_sizes[1] / DDIM;

    static int configured = 0;
    if (!configured) {
        cudaFuncSetAttribute(attn_residual_kernel,
                             cudaFuncAttributeMaxDynamicSharedMemorySize,
                             SMEM_BYTES);
        configured = 1;
    }

    attn_residual_kernel<<<BL, THREADS, SMEM_BYTES>>>(blocks, partial,
                                                      norm_scale, proj,
                                                      out, BL);
}